// round 8
// baseline (speedup 1.0000x reference)
#include <cuda_runtime.h>
#include <math.h>

#define N_NODES 6144
#define N_EDGES 196608
#define IN_F    256
#define OUT_F   128
#define EDGE_D  16
#define ALPHA   0.2f
#define CAP     128          // per-row bucket capacity (Poisson(32) tail @128 ~ e^-85)
#define WPB     4            // warps (rows) per block in attn

// ---------------- scratch (static device globals; no allocation allowed) ----
__device__ float g_h[N_NODES * OUT_F];       // transformed features
__device__ float g_s1[N_NODES];
__device__ float g_s2[N_NODES];
__device__ int   g_off[N_NODES];             // per-row fill count
__device__ int2  g_bde[N_NODES * CAP];       // bucket: (dst, eid)
__device__ float g_bes[N_NODES * CAP];       // bucket: edge score
__device__ int   g_is64 = 1;                 // dtype flag: only ever cleared

// ---------------- init: zero bucket counts + dtype probe --------------------
__global__ void init_kernel(const void* __restrict__ ei_raw) {
    int i = blockIdx.x * blockDim.x + threadIdx.x;
    if (i < N_NODES) g_off[i] = 0;
    long long v = ((const long long*)ei_raw)[i];
    if (v < 0 || v >= N_NODES) g_is64 = 0;   // benign: only ever cleared
}

__device__ __forceinline__ int load_idx(const void* ei_raw, int row, int e, int is64) {
    int v;
    if (is64) v = (int)((const long long*)ei_raw)[(long long)row * N_EDGES + e];
    else      v = ((const int*)ei_raw)[row * N_EDGES + e];
    v = v < 0 ? 0 : (v >= N_NODES ? N_NODES - 1 : v);   // never form a wild address
    return v;
}

// ---------------- SGEMM + fused s1/s2 epilogue ------------------------------
__global__ __launch_bounds__(256) void gemm_kernel(const float* __restrict__ A,
                                                   const float* __restrict__ B,
                                                   const float* __restrict__ a) {
    __shared__ float  As[32][33];     // [k][m], padded
    __shared__ float4 Bs[32][32];     // [k][col4]

    int tid = threadIdx.x;
    int ty  = tid >> 5;               // 0..7  -> rows ty*4 .. ty*4+3
    int tx  = tid & 31;               // 0..31 -> cols tx*4 .. tx*4+3
    int blockRow = blockIdx.x * 32;

    int arow = tid >> 3;              // 0..31
    int ak4  = (tid & 7) * 4;         // 0,4,...,28

    float acc[4][4] = {};

    for (int k0 = 0; k0 < IN_F; k0 += 32) {
        float4 av = *(const float4*)&A[(blockRow + arow) * IN_F + k0 + ak4];
        As[ak4 + 0][arow] = av.x;
        As[ak4 + 1][arow] = av.y;
        As[ak4 + 2][arow] = av.z;
        As[ak4 + 3][arow] = av.w;
#pragma unroll
        for (int r = 0; r < 4; r++) {
            int idx = tid + r * 256;          // 0..1023
            int kb  = idx >> 5;               // 0..31
            int cb  = idx & 31;               // 0..31
            Bs[kb][cb] = *(const float4*)&B[(k0 + kb) * OUT_F + cb * 4];
        }
        __syncthreads();
#pragma unroll
        for (int k = 0; k < 32; k++) {
            float a0 = As[k][ty * 4 + 0];
            float a1 = As[k][ty * 4 + 1];
            float a2 = As[k][ty * 4 + 2];
            float a3 = As[k][ty * 4 + 3];
            float4 bv = Bs[k][tx];
            acc[0][0] += a0 * bv.x; acc[0][1] += a0 * bv.y; acc[0][2] += a0 * bv.z; acc[0][3] += a0 * bv.w;
            acc[1][0] += a1 * bv.x; acc[1][1] += a1 * bv.y; acc[1][2] += a1 * bv.z; acc[1][3] += a1 * bv.w;
            acc[2][0] += a2 * bv.x; acc[2][1] += a2 * bv.y; acc[2][2] += a2 * bv.z; acc[2][3] += a2 * bv.w;
            acc[3][0] += a3 * bv.x; acc[3][1] += a3 * bv.y; acc[3][2] += a3 * bv.z; acc[3][3] += a3 * bv.w;
        }
        __syncthreads();
    }

#pragma unroll
    for (int r = 0; r < 4; r++) {
        float4 v = make_float4(acc[r][0], acc[r][1], acc[r][2], acc[r][3]);
        *(float4*)&g_h[(blockRow + ty * 4 + r) * OUT_F + tx * 4] = v;
    }

    float4 a1v = *(const float4*)&a[tx * 4];
    float4 a2v = *(const float4*)&a[OUT_F + tx * 4];
#pragma unroll
    for (int r = 0; r < 4; r++) {
        float p1 = acc[r][0] * a1v.x + acc[r][1] * a1v.y + acc[r][2] * a1v.z + acc[r][3] * a1v.w;
        float p2 = acc[r][0] * a2v.x + acc[r][1] * a2v.y + acc[r][2] * a2v.z + acc[r][3] * a2v.w;
#pragma unroll
        for (int o = 16; o > 0; o >>= 1) {
            p1 += __shfl_xor_sync(0xffffffffu, p1, o);
            p2 += __shfl_xor_sync(0xffffffffu, p2, o);
        }
        if (tx == 0) {
            int row = blockRow + ty * 4 + r;
            g_s1[row] = p1;
            g_s2[row] = p2;
        }
    }
}

// ---------------- fused edge pass: es + direct bucket scatter ---------------
#define E_PER 4
__global__ __launch_bounds__(256) void edge_kernel(const float* __restrict__ ef,
                                                   const float* __restrict__ a,
                                                   const void* __restrict__ ei) {
    int t = blockIdx.x * blockDim.x + threadIdx.x;
    int base = t * E_PER;
    if (base >= N_EDGES) return;
    int is64 = g_is64;

    const float* a3 = a + 2 * OUT_F;
    float4 av0 = *(const float4*)&a3[0];
    float4 av1 = *(const float4*)&a3[4];
    float4 av2 = *(const float4*)&a3[8];
    float4 av3 = *(const float4*)&a3[12];

    float4 fv[E_PER][4];
#pragma unroll
    for (int j = 0; j < E_PER; j++) {
#pragma unroll
        for (int q = 0; q < 4; q++)
            fv[j][q] = *(const float4*)&ef[(base + j) * EDGE_D + q * 4];
    }
    int src[E_PER], dst[E_PER];
#pragma unroll
    for (int j = 0; j < E_PER; j++) {
        src[j] = load_idx(ei, 0, base + j, is64);
        dst[j] = load_idx(ei, 1, base + j, is64);
    }
#pragma unroll
    for (int j = 0; j < E_PER; j++) {
        float s = fv[j][0].x * av0.x + fv[j][0].y * av0.y + fv[j][0].z * av0.z + fv[j][0].w * av0.w
                + fv[j][1].x * av1.x + fv[j][1].y * av1.y + fv[j][1].z * av1.z + fv[j][1].w * av1.w
                + fv[j][2].x * av2.x + fv[j][2].y * av2.y + fv[j][2].z * av2.z + fv[j][2].w * av2.w
                + fv[j][3].x * av3.x + fv[j][3].y * av3.y + fv[j][3].z * av3.z + fv[j][3].w * av3.w;
        int pos = atomicAdd(&g_off[src[j]], 1);
        if (pos < CAP) {
            int slot = src[j] * CAP + pos;
            g_bde[slot] = make_int2(dst[j], base + j);
            g_bes[slot] = s;
        }
    }
}

// ---------------- attention: one WARP per src row, no block barriers --------
__global__ __launch_bounds__(32 * WPB) void attn_kernel(float* __restrict__ out) {
    __shared__ int2  sde[WPB][CAP];
    __shared__ float sw [WPB][CAP];

    int w = threadIdx.x >> 5;         // warp -> row within block
    int l = threadIdx.x & 31;         // lane -> feature chunk 4l..4l+3
    int row = blockIdx.x * WPB + w;

    int d = g_off[row];
    if (d > CAP) d = CAP;

    const float4* h4 = (const float4*)g_h;

    if (d == 0) {                     // all-masked row -> uniform softmax = column mean
        float4 s = make_float4(0.f, 0.f, 0.f, 0.f);
        for (int n = 0; n < N_NODES; n++) {
            float4 hv = h4[n * 32 + l];
            s.x += hv.x; s.y += hv.y; s.z += hv.z; s.w += hv.w;
        }
        float inv = 1.f / (float)N_NODES;
        ((float4*)out)[row * 32 + l] = make_float4(s.x * inv, s.y * inv, s.z * inv, s.w * inv);
        return;
    }

    // load bucket into this warp's smem slice
    for (int k = l; k < d; k += 32) {
        sde[w][k] = g_bde[row * CAP + k];
        sw [w][k] = g_bes[row * CAP + k];
    }
    __syncwarp();

    // own entries: k = l, l+32, l+64, l+96 (nj <= 4)
    int own_dst[4], own_eid[4];
    int nj = 0;
    for (int k = l; k < d; k += 32) {
        own_dst[nj] = sde[w][k].x;
        own_eid[nj] = sde[w][k].y;
        nj++;
    }

    // dedup: duplicate (src,dst) -> last-written (max eid) edge wins
    bool win[4] = {true, true, true, true};
    for (int q = 0; q < d; q++) {
        int2 b = sde[w][q];
#pragma unroll
        for (int j = 0; j < 4; j++)
            if (j < nj && b.x == own_dst[j] && b.y > own_eid[j]) win[j] = false;
    }

    // scores + in-warp softmax
    float s1i = g_s1[row];
    float ev[4];
    float m = -1e30f;
#pragma unroll
    for (int j = 0; j < 4; j++) {
        float x = -1e30f;
        if (j < nj && win[j]) {
            x = s1i + g_s2[own_dst[j]] + sw[w][l + 32 * j];
            x = (x > 0.f) ? x : ALPHA * x;
        }
        ev[j] = x;
        m = fmaxf(m, x);
    }
#pragma unroll
    for (int o = 16; o > 0; o >>= 1) m = fmaxf(m, __shfl_xor_sync(0xffffffffu, m, o));
    float z = 0.f;
#pragma unroll
    for (int j = 0; j < 4; j++) {
        if (j < nj) {
            float wv = __expf(ev[j] - m);
            sw[w][l + 32 * j] = wv;
            z += wv;
        }
    }
#pragma unroll
    for (int o = 16; o > 0; o >>= 1) z += __shfl_xor_sync(0xffffffffu, z, o);
    float invz = 1.f / z;
    __syncwarp();

    // gather: lane l accumulates features 4l..4l+3 over all d edges
    float4 acc = make_float4(0.f, 0.f, 0.f, 0.f);
#pragma unroll 4
    for (int k = 0; k < d; k++) {
        float  wk  = sw[w][k];
        int    dst = sde[w][k].x;
        float4 hv  = h4[dst * 32 + l];
        acc.x += wk * hv.x; acc.y += wk * hv.y; acc.z += wk * hv.z; acc.w += wk * hv.w;
    }
    ((float4*)out)[row * 32 + l] =
        make_float4(acc.x * invz, acc.y * invz, acc.z * invz, acc.w * invz);
}

// ---------------- launch ----------------------------------------------------
extern "C" void kernel_launch(void* const* d_in, const int* in_sizes, int n_in,
                              void* d_out, int out_size) {
    const float* input_h       = (const float*)d_in[0];
    const void*  edge_index    = (const void*)d_in[1];
    const float* edge_features = (const float*)d_in[2];
    const float* W             = (const float*)d_in[3];
    const float* a             = (const float*)d_in[4];
    float* out = (float*)d_out;

    init_kernel<<<8, 1024>>>(edge_index);
    gemm_kernel<<<N_NODES / 32, 256>>>(input_h, W, a);
    edge_kernel<<<N_EDGES / (256 * E_PER), 256>>>(edge_features, a, edge_index);
    attn_kernel<<<N_NODES / WPB, 32 * WPB>>>(out);
}

// round 10
// speedup vs baseline: 1.0673x; 1.0673x over previous
#include <cuda_runtime.h>
#include <math.h>

#define N_NODES 6144
#define N_EDGES 196608
#define IN_F    256
#define OUT_F   128
#define EDGE_D  16
#define ALPHA   0.2f
#define CAP     128          // per-row bucket capacity (Poisson(32) tail @128 ~ e^-85)

#define GEMM_BLOCKS (N_NODES / 32)      // 192
#define INIT_BLOCKS 24                  // 24 * 256 = 6144
#define K1_BLOCKS   (GEMM_BLOCKS + INIT_BLOCKS)

// ---------------- scratch (static device globals; no allocation allowed) ----
__device__ float g_h[N_NODES * OUT_F];       // transformed features
__device__ float g_s1[N_NODES];
__device__ float g_s2[N_NODES];
__device__ int   g_off[N_NODES];             // per-row fill count (zero-init + re-zeroed)
__device__ int   g_bdst[N_NODES * CAP];      // bucket: dst node
__device__ int   g_beid[N_NODES * CAP];      // bucket: edge id (dedup tie-break)
__device__ float g_bes [N_NODES * CAP];      // bucket: edge score
__device__ int   g_is64 = 1;                 // dtype flag: only ever cleared

__device__ __forceinline__ int load_idx(const void* ei_raw, int row, int e, int is64) {
    int v;
    if (is64) v = (int)((const long long*)ei_raw)[(long long)row * N_EDGES + e];
    else      v = ((const int*)ei_raw)[row * N_EDGES + e];
    v = v < 0 ? 0 : (v >= N_NODES ? N_NODES - 1 : v);   // never form a wild address
    return v;
}

// ---------------- kernel 1: SGEMM (+s1/s2 epilogue) | init tail blocks ------
// Blocks [0,192): g_h = input_h @ W, s1 = h@a1, s2 = h@a2.
// Blocks [192,216): zero g_off + dtype probe (edge_kernel runs in a later
// launch, so ordering is safe; gemm never touches g_off / g_is64).
__global__ __launch_bounds__(256) void gemm_init_kernel(const float* __restrict__ A,
                                                        const float* __restrict__ B,
                                                        const float* __restrict__ a,
                                                        const void* __restrict__ ei_raw) {
    if (blockIdx.x >= GEMM_BLOCKS) {
        int i = (blockIdx.x - GEMM_BLOCKS) * 256 + threadIdx.x;   // 0..6143
        g_off[i] = 0;
        long long v = ((const long long*)ei_raw)[i];
        if (v < 0 || v >= N_NODES) g_is64 = 0;   // benign: only ever cleared
        return;
    }

    __shared__ float  As[32][33];     // [k][m], padded
    __shared__ float4 Bs[32][32];     // [k][col4]

    int tid = threadIdx.x;
    int ty  = tid >> 5;               // 0..7  -> rows ty*4 .. ty*4+3
    int tx  = tid & 31;               // 0..31 -> cols tx*4 .. tx*4+3
    int blockRow = blockIdx.x * 32;

    int arow = tid >> 3;              // 0..31
    int ak4  = (tid & 7) * 4;         // 0,4,...,28

    float acc[4][4] = {};

    for (int k0 = 0; k0 < IN_F; k0 += 32) {
        float4 av = *(const float4*)&A[(blockRow + arow) * IN_F + k0 + ak4];
        As[ak4 + 0][arow] = av.x;
        As[ak4 + 1][arow] = av.y;
        As[ak4 + 2][arow] = av.z;
        As[ak4 + 3][arow] = av.w;
#pragma unroll
        for (int r = 0; r < 4; r++) {
            int idx = tid + r * 256;          // 0..1023
            int kb  = idx >> 5;               // 0..31
            int cb  = idx & 31;               // 0..31
            Bs[kb][cb] = *(const float4*)&B[(k0 + kb) * OUT_F + cb * 4];
        }
        __syncthreads();
#pragma unroll
        for (int k = 0; k < 32; k++) {
            float a0 = As[k][ty * 4 + 0];
            float a1 = As[k][ty * 4 + 1];
            float a2 = As[k][ty * 4 + 2];
            float a3 = As[k][ty * 4 + 3];
            float4 bv = Bs[k][tx];
            acc[0][0] += a0 * bv.x; acc[0][1] += a0 * bv.y; acc[0][2] += a0 * bv.z; acc[0][3] += a0 * bv.w;
            acc[1][0] += a1 * bv.x; acc[1][1] += a1 * bv.y; acc[1][2] += a1 * bv.z; acc[1][3] += a1 * bv.w;
            acc[2][0] += a2 * bv.x; acc[2][1] += a2 * bv.y; acc[2][2] += a2 * bv.z; acc[2][3] += a2 * bv.w;
            acc[3][0] += a3 * bv.x; acc[3][1] += a3 * bv.y; acc[3][2] += a3 * bv.z; acc[3][3] += a3 * bv.w;
        }
        __syncthreads();
    }

#pragma unroll
    for (int r = 0; r < 4; r++) {
        float4 v = make_float4(acc[r][0], acc[r][1], acc[r][2], acc[r][3]);
        *(float4*)&g_h[(blockRow + ty * 4 + r) * OUT_F + tx * 4] = v;
    }

    float4 a1v = *(const float4*)&a[tx * 4];
    float4 a2v = *(const float4*)&a[OUT_F + tx * 4];
#pragma unroll
    for (int r = 0; r < 4; r++) {
        float p1 = acc[r][0] * a1v.x + acc[r][1] * a1v.y + acc[r][2] * a1v.z + acc[r][3] * a1v.w;
        float p2 = acc[r][0] * a2v.x + acc[r][1] * a2v.y + acc[r][2] * a2v.z + acc[r][3] * a2v.w;
#pragma unroll
        for (int o = 16; o > 0; o >>= 1) {
            p1 += __shfl_xor_sync(0xffffffffu, p1, o);
            p2 += __shfl_xor_sync(0xffffffffu, p2, o);
        }
        if (tx == 0) {
            int row = blockRow + ty * 4 + r;
            g_s1[row] = p1;
            g_s2[row] = p2;
        }
    }
}

// ---------------- fused edge pass: es + direct bucket scatter ---------------
#define E_PER 4
__global__ __launch_bounds__(256) void edge_kernel(const float* __restrict__ ef,
                                                   const float* __restrict__ a,
                                                   const void* __restrict__ ei) {
    int t = blockIdx.x * blockDim.x + threadIdx.x;
    int base = t * E_PER;
    if (base >= N_EDGES) return;
    int is64 = g_is64;

    const float* a3 = a + 2 * OUT_F;
    float4 av0 = *(const float4*)&a3[0];
    float4 av1 = *(const float4*)&a3[4];
    float4 av2 = *(const float4*)&a3[8];
    float4 av3 = *(const float4*)&a3[12];

    float4 fv[E_PER][4];
#pragma unroll
    for (int j = 0; j < E_PER; j++) {
#pragma unroll
        for (int q = 0; q < 4; q++)
            fv[j][q] = *(const float4*)&ef[(base + j) * EDGE_D + q * 4];
    }
    int src[E_PER], dst[E_PER];
#pragma unroll
    for (int j = 0; j < E_PER; j++) {
        src[j] = load_idx(ei, 0, base + j, is64);
        dst[j] = load_idx(ei, 1, base + j, is64);
    }
#pragma unroll
    for (int j = 0; j < E_PER; j++) {
        float s = fv[j][0].x * av0.x + fv[j][0].y * av0.y + fv[j][0].z * av0.z + fv[j][0].w * av0.w
                + fv[j][1].x * av1.x + fv[j][1].y * av1.y + fv[j][1].z * av1.z + fv[j][1].w * av1.w
                + fv[j][2].x * av2.x + fv[j][2].y * av2.y + fv[j][2].z * av2.z + fv[j][2].w * av2.w
                + fv[j][3].x * av3.x + fv[j][3].y * av3.y + fv[j][3].z * av3.z + fv[j][3].w * av3.w;
        int pos = atomicAdd(&g_off[src[j]], 1);
        if (pos < CAP) {
            int slot = src[j] * CAP + pos;
            g_bdst[slot] = dst[j];
            g_beid[slot] = base + j;
            g_bes [slot] = s;
        }
    }
}

// ---------------- attention (R7 structure: block per row, measured best) ----
// Softmax by warp 0 (strided LDS + shfl). Gather: 4 warps x 32 lanes, warp g
// takes edges k = g, g+4, ..., lane l owns features 4l..4l+3 (float4 loads).
__global__ __launch_bounds__(128) void attn_kernel(float* __restrict__ out) {
    __shared__ int    sdst[CAP];
    __shared__ int    seid[CAP];
    __shared__ float  sw[CAP];
    __shared__ float  sinvz;
    __shared__ float4 racc[4][32];

    int i = blockIdx.x;
    int t = threadIdx.x;
    int g = t >> 5;                   // warp / edge-group
    int l = t & 31;                   // lane / feature chunk
    int d = g_off[i];
    if (d > CAP) d = CAP;

    if (d == 0) {                     // all-masked row -> uniform softmax = column mean
        float s = 0.f;
        for (int n = 0; n < N_NODES; n++) s += g_h[n * OUT_F + t];
        out[i * OUT_F + t] = s / (float)N_NODES;
        return;
    }

    float s1i = g_s1[i];
    if (t < d) {
        int slot = i * CAP + t;
        sdst[t] = g_bdst[slot];
        seid[t] = g_beid[slot];
        sw[t]   = g_bes [slot];
    }
    __syncthreads();

    if (t < d) {
        int dst = sdst[t];
        int eid = seid[t];
        // dedup duplicate (src,dst): last-written (max eid) edge wins.
        bool win = true;
        for (int k = 0; k < d; k++)
            if (sdst[k] == dst && seid[k] > eid) win = false;
        float e = -1e30f;
        if (win) {
            e = s1i + g_s2[dst] + sw[t];
            e = (e > 0.f) ? e : ALPHA * e;
        }
        sw[t] = e;
    }
    __syncthreads();

    // warp 0: row softmax (max, exp, sum) over d entries
    if (g == 0) {
        float v[4];
        float m = -1e30f;
#pragma unroll
        for (int j = 0; j < 4; j++) {
            int k = l + 32 * j;
            v[j] = (k < d) ? sw[k] : -1e30f;
            m = fmaxf(m, v[j]);
        }
#pragma unroll
        for (int o = 16; o > 0; o >>= 1) m = fmaxf(m, __shfl_xor_sync(0xffffffffu, m, o));
        float z = 0.f;
#pragma unroll
        for (int j = 0; j < 4; j++) {
            int k = l + 32 * j;
            if (k < d) {
                float w = __expf(v[j] - m);
                sw[k] = w;
                z += w;
            }
        }
#pragma unroll
        for (int o = 16; o > 0; o >>= 1) z += __shfl_xor_sync(0xffffffffu, z, o);
        if (l == 0) sinvz = 1.f / z;
    }
    __syncthreads();

    // gather: warp g handles edges g, g+4, ...; float4 per lane
    const float4* h4 = (const float4*)g_h;
    float4 acc = make_float4(0.f, 0.f, 0.f, 0.f);
    for (int k = g; k < d; k += 4) {
        float  wk  = sw[k];
        int    dst = sdst[k];
        float4 hv  = h4[dst * 32 + l];
        acc.x += wk * hv.x; acc.y += wk * hv.y; acc.z += wk * hv.z; acc.w += wk * hv.w;
    }
    racc[g][l] = acc;
    __syncthreads();

    if (g == 0) {
        float4 a0 = racc[0][l], a1 = racc[1][l], a2 = racc[2][l], a3 = racc[3][l];
        float invz = sinvz;
        float4 o;
        o.x = (a0.x + a1.x + a2.x + a3.x) * invz;
        o.y = (a0.y + a1.y + a2.y + a3.y) * invz;
        o.z = (a0.z + a1.z + a2.z + a3.z) * invz;
        o.w = (a0.w + a1.w + a2.w + a3.w) * invz;
        ((float4*)out)[i * 32 + l] = o;
    }
}

// ---------------- launch ----------------------------------------------------
extern "C" void kernel_launch(void* const* d_in, const int* in_sizes, int n_in,
                              void* d_out, int out_size) {
    const float* input_h       = (const float*)d_in[0];
    const void*  edge_index    = (const void*)d_in[1];
    const float* edge_features = (const float*)d_in[2];
    const float* W             = (const float*)d_in[3];
    const float* a             = (const float*)d_in[4];
    float* out = (float*)d_out;

    gemm_init_kernel<<<K1_BLOCKS, 256>>>(input_h, W, a, edge_index);
    edge_kernel<<<N_EDGES / (256 * E_PER), 256>>>(edge_features, a, edge_index);
    attn_kernel<<<N_NODES, 128>>>(out);
}